// round 1
// baseline (speedup 1.0000x reference)
#include <cuda_runtime.h>
#include <math.h>

#define N_TOK 4096   // B*T
#define DIM   1024   // D
#define FF    4096   // F
#define NE    8      // experts
#define NA    8192   // N_TOK * topk(2) assignments

// Static device scratch (no allocations allowed in kernel_launch)
__device__ float g_h[(size_t)NA * FF];    // gelu(x@W1+b1) per assignment, 134 MB
__device__ float g_y[(size_t)NA * DIM];   // gate*(h@W2+b2) per assignment, 33.5 MB
__device__ int   g_cnt[NE];               // rows per expert
__device__ int   g_rows[NE * N_TOK];      // assignment slot ids per expert
__device__ float g_gate[NA];              // gate weight per assignment slot

__global__ void zero_cnt_kernel() {
    if (threadIdx.x < NE) g_cnt[threadIdx.x] = 0;
}

// One warp per token: logits (8 dots of length 1024), top-2, softmax over the 2,
// scatter assignment slots into per-expert lists.
__global__ void gate_kernel(const float* __restrict__ x, const float* __restrict__ Wg) {
    int warp = (blockIdx.x * blockDim.x + threadIdx.x) >> 5;
    int lane = threadIdx.x & 31;
    if (warp >= N_TOK) return;
    const float* xr = x + (size_t)warp * DIM;
    float acc[NE];
#pragma unroll
    for (int e = 0; e < NE; e++) acc[e] = 0.f;
    for (int d = lane * 4; d < DIM; d += 128) {
        float4 xv = *(const float4*)(xr + d);
        float xs[4] = {xv.x, xv.y, xv.z, xv.w};
#pragma unroll
        for (int j = 0; j < 4; j++) {
            const float* wr = Wg + (size_t)(d + j) * NE;
#pragma unroll
            for (int e = 0; e < NE; e++) acc[e] += xs[j] * wr[e];
        }
    }
#pragma unroll
    for (int e = 0; e < NE; e++) {
#pragma unroll
        for (int o = 16; o > 0; o >>= 1)
            acc[e] += __shfl_xor_sync(0xffffffffu, acc[e], o);
    }
    if (lane == 0) {
        int i0 = 0; float v0 = acc[0];
#pragma unroll
        for (int e = 1; e < NE; e++) if (acc[e] > v0) { v0 = acc[e]; i0 = e; }
        int i1 = -1; float v1 = -1e30f;
#pragma unroll
        for (int e = 0; e < NE; e++) if (e != i0 && acc[e] > v1) { v1 = acc[e]; i1 = e; }
        // softmax over the two selected logits (others are -inf in the reference)
        float e1 = expf(v1 - v0);
        float inv = 1.f / (1.f + e1);
        float g0 = inv, g1 = e1 * inv;
        int a0 = warp * 2, a1 = warp * 2 + 1;
        g_gate[a0] = g0;
        g_gate[a1] = g1;
        int p0 = atomicAdd(&g_cnt[i0], 1);
        g_rows[i0 * N_TOK + p0] = a0;
        int p1 = atomicAdd(&g_cnt[i1], 1);
        g_rows[i1 * N_TOK + p1] = a1;
    }
}

__device__ __forceinline__ float gelu_tanh(float v) {
    // jax.nn.gelu default: approximate=True (tanh form)
    float u = 0.7978845608028654f * (v + 0.044715f * v * v * v);
    return 0.5f * v * (1.f + tanhf(u));
}

// FFN1: for expert e, H[rows, FF] = gelu( Xgathered[rows, DIM] @ W1_e + b1_e )
// 128x128 tile, BK=8, 256 threads, 8x8 per thread.
__global__ __launch_bounds__(256, 2)
void ffn1_kernel(const float* __restrict__ x, const float* __restrict__ W1,
                 const float* __restrict__ b1) {
    int e = blockIdx.z;
    int cnt = g_cnt[e];
    int row0 = blockIdx.y * 128;
    if (row0 >= cnt) return;
    int col0 = blockIdx.x * 128;
    const float* Bw = W1 + (size_t)e * DIM * FF;

    __shared__ float As[8][132];   // padded: conflict-free transpose store
    __shared__ float Bs[8][132];

    int tid = threadIdx.x;
    int tx = tid & 15, ty = tid >> 4;
    int aRow = tid >> 1, aK = (tid & 1) * 4;
    int bK = tid >> 5, bN = (tid & 31) * 4;

    const float* arow = nullptr;
    int gr = row0 + aRow;
    if (gr < cnt) {
        int a = g_rows[e * N_TOK + gr];
        arow = x + (size_t)(a >> 1) * DIM;   // token = slot >> 1
    }

    float acc[8][8];
#pragma unroll
    for (int i = 0; i < 8; i++)
#pragma unroll
        for (int j = 0; j < 8; j++) acc[i][j] = 0.f;

    for (int k0 = 0; k0 < DIM; k0 += 8) {
        float4 av = arow ? *(const float4*)(arow + k0 + aK)
                         : make_float4(0.f, 0.f, 0.f, 0.f);
        As[aK + 0][aRow] = av.x;
        As[aK + 1][aRow] = av.y;
        As[aK + 2][aRow] = av.z;
        As[aK + 3][aRow] = av.w;
        *(float4*)&Bs[bK][bN] =
            *(const float4*)(Bw + (size_t)(k0 + bK) * FF + col0 + bN);
        __syncthreads();
#pragma unroll
        for (int k = 0; k < 8; k++) {
            float ar[8], br[8];
            *(float4*)&ar[0] = *(const float4*)&As[k][ty * 4];
            *(float4*)&ar[4] = *(const float4*)&As[k][64 + ty * 4];
            *(float4*)&br[0] = *(const float4*)&Bs[k][tx * 4];
            *(float4*)&br[4] = *(const float4*)&Bs[k][64 + tx * 4];
#pragma unroll
            for (int i = 0; i < 8; i++)
#pragma unroll
                for (int j = 0; j < 8; j++) acc[i][j] += ar[i] * br[j];
        }
        __syncthreads();
    }

#pragma unroll
    for (int i = 0; i < 8; i++) {
        int lr = (i < 4) ? (ty * 4 + i) : (64 + ty * 4 + i - 4);
        int r = row0 + lr;
        if (r >= cnt) continue;
        int a = g_rows[e * N_TOK + r];
        float* hrow = g_h + (size_t)a * FF + col0;
#pragma unroll
        for (int jh = 0; jh < 2; jh++) {
            int cb = jh ? (64 + tx * 4) : (tx * 4);
            float4 o;
            float* op = (float*)&o;
#pragma unroll
            for (int j = 0; j < 4; j++) {
                float v = acc[i][jh * 4 + j] + b1[e * FF + col0 + cb + j];
                op[j] = gelu_tanh(v);
            }
            *(float4*)(hrow + cb) = o;
        }
    }
}

// FFN2: Y[rows, DIM] = gate * ( H[rows, FF] @ W2_e + b2_e ), written to g_y[slot]
__global__ __launch_bounds__(256, 2)
void ffn2_kernel(const float* __restrict__ W2, const float* __restrict__ b2) {
    int e = blockIdx.z;
    int cnt = g_cnt[e];
    int row0 = blockIdx.y * 128;
    if (row0 >= cnt) return;
    int col0 = blockIdx.x * 128;
    const float* Bw = W2 + (size_t)e * FF * DIM;

    __shared__ float As[8][132];
    __shared__ float Bs[8][132];

    int tid = threadIdx.x;
    int tx = tid & 15, ty = tid >> 4;
    int aRow = tid >> 1, aK = (tid & 1) * 4;
    int bK = tid >> 5, bN = (tid & 31) * 4;

    const float* arow = nullptr;
    int gr = row0 + aRow;
    if (gr < cnt) {
        int a = g_rows[e * N_TOK + gr];
        arow = g_h + (size_t)a * FF;
    }

    float acc[8][8];
#pragma unroll
    for (int i = 0; i < 8; i++)
#pragma unroll
        for (int j = 0; j < 8; j++) acc[i][j] = 0.f;

    for (int k0 = 0; k0 < FF; k0 += 8) {
        float4 av = arow ? *(const float4*)(arow + k0 + aK)
                         : make_float4(0.f, 0.f, 0.f, 0.f);
        As[aK + 0][aRow] = av.x;
        As[aK + 1][aRow] = av.y;
        As[aK + 2][aRow] = av.z;
        As[aK + 3][aRow] = av.w;
        *(float4*)&Bs[bK][bN] =
            *(const float4*)(Bw + (size_t)(k0 + bK) * DIM + col0 + bN);
        __syncthreads();
#pragma unroll
        for (int k = 0; k < 8; k++) {
            float ar[8], br[8];
            *(float4*)&ar[0] = *(const float4*)&As[k][ty * 4];
            *(float4*)&ar[4] = *(const float4*)&As[k][64 + ty * 4];
            *(float4*)&br[0] = *(const float4*)&Bs[k][tx * 4];
            *(float4*)&br[4] = *(const float4*)&Bs[k][64 + tx * 4];
#pragma unroll
            for (int i = 0; i < 8; i++)
#pragma unroll
                for (int j = 0; j < 8; j++) acc[i][j] += ar[i] * br[j];
        }
        __syncthreads();
    }

#pragma unroll
    for (int i = 0; i < 8; i++) {
        int lr = (i < 4) ? (ty * 4 + i) : (64 + ty * 4 + i - 4);
        int r = row0 + lr;
        if (r >= cnt) continue;
        int a = g_rows[e * N_TOK + r];
        float gate = g_gate[a];
        float* yrow = g_y + (size_t)a * DIM + col0;
#pragma unroll
        for (int jh = 0; jh < 2; jh++) {
            int cb = jh ? (64 + tx * 4) : (tx * 4);
            float4 o;
            float* op = (float*)&o;
#pragma unroll
            for (int j = 0; j < 4; j++) {
                float v = acc[i][jh * 4 + j] + b2[e * DIM + col0 + cb + j];
                op[j] = gate * v;
            }
            *(float4*)(yrow + cb) = o;
        }
    }
}

// out[t] = y[slot 2t] + y[slot 2t+1]   (fixed order -> deterministic)
__global__ void combine_kernel(float* __restrict__ out) {
    int i = blockIdx.x * blockDim.x + threadIdx.x;   // over N_TOK*DIM/4
    if (i >= N_TOK * DIM / 4) return;
    int t = i / (DIM / 4);
    int c4 = i % (DIM / 4);
    const float4* y0 = (const float4*)(g_y + (size_t)(2 * t) * DIM) + c4;
    const float4* y1 = (const float4*)(g_y + (size_t)(2 * t + 1) * DIM) + c4;
    float4 a = *y0, b = *y1;
    float4 o = make_float4(a.x + b.x, a.y + b.y, a.z + b.z, a.w + b.w);
    ((float4*)out)[i] = o;
}

extern "C" void kernel_launch(void* const* d_in, const int* in_sizes, int n_in,
                              void* d_out, int out_size) {
    const float* x  = (const float*)d_in[0];
    const float* Wg = (const float*)d_in[1];
    const float* W1 = (const float*)d_in[2];
    const float* b1 = (const float*)d_in[3];
    const float* W2 = (const float*)d_in[4];
    const float* b2 = (const float*)d_in[5];
    // d_in[6] = topk (hardcoded 2)
    float* out = (float*)d_out;

    zero_cnt_kernel<<<1, 32>>>();
    gate_kernel<<<(N_TOK * 32) / 256, 256>>>(x, Wg);

    dim3 g1(FF / 128, N_TOK / 128, NE);   // (32, 32, 8), empty tiles exit early
    ffn1_kernel<<<g1, 256>>>(x, W1, b1);

    dim3 g2(DIM / 128, N_TOK / 128, NE);  // (8, 32, 8)
    ffn2_kernel<<<g2, 256>>>(W2, b2);

    combine_kernel<<<(N_TOK * DIM / 4 + 255) / 256, 256>>>(out);
}